// round 1
// baseline (speedup 1.0000x reference)
#include <cuda_runtime.h>
#include <cuda_bf16.h>
#include <cstdint>

// ---------------------------------------------------------------------------
// QLoRABigNet: 6 blocks x (3 QLoRA linears + relus) + residual + LN
// C=1024, G=128, R=32, N=8192 rows, 18 layers.
// Round 1: fp32 SIMT implementation.
//   - dequant all weights once per launch into g_W (fp32)
//   - per layer: lora u = x@A^T (split-K, two-stage deterministic),
//     main SGEMM y = x@W^T + b + u@B^T (+res)(+relu) fused epilogue
//   - layernorm per row
// ---------------------------------------------------------------------------

#define NROWS 8192
#define CDIM  1024
#define NLAYER 18
#define RDIM  32

// scratch (device globals: allocation-free rule)
__device__ float g_W[(size_t)NLAYER * CDIM * CDIM];   // 75.5 MB dequantized weights
__device__ float g_h[(size_t)NROWS * CDIM];           // residual stream
__device__ float g_t1[(size_t)NROWS * CDIM];
__device__ float g_t2[(size_t)NROWS * CDIM];
__device__ float g_upart[(size_t)8 * NROWS * RDIM];   // split-K partials for lora u
__device__ float g_u[(size_t)NROWS * RDIM];           // u = x @ A^T

// ---------------------------------------------------------------------------
// Dequant: W[l][o][i] = (q - 8) * scales[l][o][i/128], vectorized by 4.
// ---------------------------------------------------------------------------
__global__ void dequant_k(const int* __restrict__ qw,
                          const float* __restrict__ scales,
                          float* __restrict__ Wout, int total4)
{
    int idx = blockIdx.x * blockDim.x + threadIdx.x;
    if (idx >= total4) return;
    int4 q = ((const int4*)qw)[idx];
    size_t base = (size_t)idx * 4;
    int i = (int)(base & 1023);          // position within C_in
    size_t ro = base >> 10;              // l*1024 + o
    float s = scales[ro * 8 + (i >> 7)]; // 4 consecutive i never cross a group
    float4 w;
    w.x = (float)(q.x - 8) * s;
    w.y = (float)(q.y - 8) * s;
    w.z = (float)(q.z - 8) * s;
    w.w = (float)(q.w - 8) * s;
    ((float4*)Wout)[idx] = w;
}

// ---------------------------------------------------------------------------
// LoRA stage 1: partial u over a K-split of 128.
// grid (64 row-tiles, 8 k-splits), 256 threads.
// ---------------------------------------------------------------------------
__global__ void lora_u_partial(const float* __restrict__ X,
                               const float* __restrict__ A,   // [32][1024]
                               float* __restrict__ Up)        // [8][NROWS][32]
{
    __shared__ float sA[32 * 33];
    __shared__ float sX[128 * 33];
    int tid = threadIdx.x;
    int m0 = blockIdx.x * 128;
    int k0 = blockIdx.y * 128;
    int r  = tid & 31;
    int ng = tid >> 5;              // 0..7 -> rows ng*16 .. +15
    float acc[16];
    #pragma unroll
    for (int j = 0; j < 16; j++) acc[j] = 0.f;

    for (int kc = 0; kc < 4; ++kc) {
        int kb = k0 + kc * 32;
        #pragma unroll
        for (int s = 0; s < 4; s++) {
            int f = tid + s * 256;           // 0..1023
            int rr = f >> 5, kk = f & 31;
            sA[rr * 33 + kk] = A[rr * 1024 + kb + kk];
        }
        #pragma unroll
        for (int s = 0; s < 16; s++) {
            int f = tid + s * 256;
            int rr = f >> 5, kk = f & 31;
            sX[rr * 33 + kk] = X[(size_t)(m0 + rr) * CDIM + kb + kk];
        }
        __syncthreads();
        #pragma unroll
        for (int k = 0; k < 32; k++) {
            float a = sA[r * 33 + k];
            #pragma unroll
            for (int j = 0; j < 16; j++)
                acc[j] += sX[(ng * 16 + j) * 33 + k] * a;
        }
        __syncthreads();
    }
    #pragma unroll
    for (int j = 0; j < 16; j++)
        Up[((size_t)blockIdx.y * NROWS + m0 + ng * 16 + j) * RDIM + r] = acc[j];
}

// LoRA stage 2: deterministic fixed-order reduction of the 8 partials.
__global__ void lora_u_reduce(const float* __restrict__ Up, float* __restrict__ U)
{
    int idx = blockIdx.x * blockDim.x + threadIdx.x;   // 0 .. 262143
    float s = 0.f;
    #pragma unroll
    for (int p = 0; p < 8; p++)
        s += Up[(size_t)p * (NROWS * RDIM) + idx];
    U[idx] = s;
}

// ---------------------------------------------------------------------------
// Main fused SGEMM: Out = [relu]( X @ W^T + bias + U @ B^T [+ Res] )
// BM=BN=128, BK=16, TM=TN=8, 256 threads, double-buffered smem.
// grid: (CDIM/128=8, NROWS/128=64)
// ---------------------------------------------------------------------------
__global__ __launch_bounds__(256, 2)
void gemm_fused(const float* __restrict__ X,
                const float* __restrict__ W,     // [1024][1024], o-major, i contiguous
                const float* __restrict__ bias,  // [1024]
                const float* __restrict__ U,     // [NROWS][32]
                const float* __restrict__ Bl,    // [1024][32]
                const float* __restrict__ Res,   // [NROWS][1024] or null
                float* __restrict__ Out,
                int do_relu)
{
    __shared__ __align__(16) float smem[8448];
    float* As = smem;          // 2 x [16][128]
    float* Bs = smem + 4096;   // 2 x [16][128]

    const int tid = threadIdx.x;
    const int tx = tid & 15;
    const int ty = tid >> 4;
    const int m0 = blockIdx.y * 128;
    const int o0 = blockIdx.x * 128;

    float acc[8][8];
    #pragma unroll
    for (int i = 0; i < 8; i++)
        #pragma unroll
        for (int j = 0; j < 8; j++) acc[i][j] = 0.f;

    const int lrow = tid >> 2;   // 0..63
    const int lc4  = tid & 3;    // 0..3
    const float* Xg  = X + (size_t)(m0 + lrow) * CDIM + lc4 * 4;
    const float* Xg2 = Xg + (size_t)64 * CDIM;
    const float* Wg  = W + (size_t)(o0 + lrow) * CDIM + lc4 * 4;
    const float* Wg2 = Wg + (size_t)64 * CDIM;

    // prologue: tile 0 -> buffer 0
    {
        float4 a0 = *(const float4*)Xg;
        float4 a1 = *(const float4*)Xg2;
        float4 b0 = *(const float4*)Wg;
        float4 b1 = *(const float4*)Wg2;
        #pragma unroll
        for (int j = 0; j < 4; j++) {
            As[(lc4 * 4 + j) * 128 + lrow]      = ((float*)&a0)[j];
            As[(lc4 * 4 + j) * 128 + lrow + 64] = ((float*)&a1)[j];
            Bs[(lc4 * 4 + j) * 128 + lrow]      = ((float*)&b0)[j];
            Bs[(lc4 * 4 + j) * 128 + lrow + 64] = ((float*)&b1)[j];
        }
    }
    __syncthreads();

    const int nTiles = CDIM / 16;   // 64
    for (int t = 0; t < nTiles; ++t) {
        int cur = t & 1;
        float4 a0, a1, b0, b1;
        if (t < nTiles - 1) {
            int ko = (t + 1) * 16;
            a0 = *(const float4*)(Xg  + ko);
            a1 = *(const float4*)(Xg2 + ko);
            b0 = *(const float4*)(Wg  + ko);
            b1 = *(const float4*)(Wg2 + ko);
        }
        const float* Ac = As + cur * 2048;
        const float* Bc = Bs + cur * 2048;
        #pragma unroll
        for (int k = 0; k < 16; k++) {
            float a[8], b[8];
            *(float4*)&a[0] = *(const float4*)&Ac[k * 128 + ty * 8];
            *(float4*)&a[4] = *(const float4*)&Ac[k * 128 + ty * 8 + 4];
            *(float4*)&b[0] = *(const float4*)&Bc[k * 128 + tx * 8];
            *(float4*)&b[4] = *(const float4*)&Bc[k * 128 + tx * 8 + 4];
            #pragma unroll
            for (int i = 0; i < 8; i++)
                #pragma unroll
                for (int j = 0; j < 8; j++)
                    acc[i][j] += a[i] * b[j];
        }
        if (t < nTiles - 1) {
            int nb = cur ^ 1;
            float* An = As + nb * 2048;
            float* Bn = Bs + nb * 2048;
            #pragma unroll
            for (int j = 0; j < 4; j++) {
                An[(lc4 * 4 + j) * 128 + lrow]      = ((float*)&a0)[j];
                An[(lc4 * 4 + j) * 128 + lrow + 64] = ((float*)&a1)[j];
                Bn[(lc4 * 4 + j) * 128 + lrow]      = ((float*)&b0)[j];
                Bn[(lc4 * 4 + j) * 128 + lrow + 64] = ((float*)&b1)[j];
            }
        }
        __syncthreads();
    }

    // ---- epilogue: LoRA rank-32 contribution (reuse smem) ----
    // Su: [128][32] at smem[0], Sb: [128] rows, stride 33, at smem+4096
    {
        const float4* Ug = (const float4*)(U + (size_t)m0 * RDIM);
        float4* Su4 = (float4*)smem;
        #pragma unroll
        for (int s = 0; s < 4; s++)
            Su4[tid + s * 256] = Ug[tid + s * 256];
        #pragma unroll
        for (int s = 0; s < 4; s++) {
            int f = tid + s * 256;       // float4 index, row = f/8
            int row = f >> 3, c4 = f & 7;
            float4 v = *(const float4*)(Bl + (size_t)(o0 + row) * RDIM + c4 * 4);
            float* dst = smem + 4096 + row * 33 + c4 * 4;
            dst[0] = v.x; dst[1] = v.y; dst[2] = v.z; dst[3] = v.w;
        }
    }
    __syncthreads();

    #pragma unroll
    for (int r = 0; r < RDIM; r++) {
        float uu[8], bb[8];
        #pragma unroll
        for (int i = 0; i < 8; i++) uu[i] = smem[(ty * 8 + i) * 32 + r];
        #pragma unroll
        for (int j = 0; j < 8; j++) bb[j] = smem[4096 + (tx * 8 + j) * 33 + r];
        #pragma unroll
        for (int i = 0; i < 8; i++)
            #pragma unroll
            for (int j = 0; j < 8; j++)
                acc[i][j] += uu[i] * bb[j];
    }

    // bias + residual + relu + store
    float bs[8];
    #pragma unroll
    for (int j = 0; j < 8; j++) bs[j] = bias[o0 + tx * 8 + j];

    #pragma unroll
    for (int i = 0; i < 8; i++) {
        int row = m0 + ty * 8 + i;
        float* op = Out + (size_t)row * CDIM + o0 + tx * 8;
        float rv[8];
        if (Res) {
            const float* rp = Res + (size_t)row * CDIM + o0 + tx * 8;
            *(float4*)&rv[0] = *(const float4*)&rp[0];
            *(float4*)&rv[4] = *(const float4*)&rp[4];
        }
        float o[8];
        #pragma unroll
        for (int j = 0; j < 8; j++) {
            float v = acc[i][j] + bs[j];
            if (Res) v += rv[j];
            if (do_relu) v = fmaxf(v, 0.f);
            o[j] = v;
        }
        *(float4*)&op[0] = *(const float4*)&o[0];
        *(float4*)&op[4] = *(const float4*)&o[4];
    }
}

// ---------------------------------------------------------------------------
// LayerNorm, one CTA (256 threads) per row, in-place.
// ---------------------------------------------------------------------------
__global__ void layernorm_k(float* __restrict__ H,
                            const float* __restrict__ g,
                            const float* __restrict__ b)
{
    __shared__ float red[16];
    int row = blockIdx.x;
    float4* hp = (float4*)(H + (size_t)row * CDIM);
    int tid = threadIdx.x;      // 256, each handles 4 floats
    float4 x = hp[tid];

    float s = x.x + x.y + x.z + x.w;
    #pragma unroll
    for (int o = 16; o > 0; o >>= 1) s += __shfl_xor_sync(0xffffffffu, s, o);
    if ((tid & 31) == 0) red[tid >> 5] = s;
    __syncthreads();
    float tot = 0.f;
    #pragma unroll
    for (int w = 0; w < 8; w++) tot += red[w];
    float mean = tot * (1.f / 1024.f);

    float d0 = x.x - mean, d1 = x.y - mean, d2 = x.z - mean, d3 = x.w - mean;
    float sq = d0 * d0 + d1 * d1 + d2 * d2 + d3 * d3;
    #pragma unroll
    for (int o = 16; o > 0; o >>= 1) sq += __shfl_xor_sync(0xffffffffu, sq, o);
    if ((tid & 31) == 0) red[8 + (tid >> 5)] = sq;
    __syncthreads();
    float tot2 = 0.f;
    #pragma unroll
    for (int w = 0; w < 8; w++) tot2 += red[8 + w];
    float inv = rsqrtf(tot2 * (1.f / 1024.f) + 1e-5f);

    float4 gg = ((const float4*)g)[tid];
    float4 bb = ((const float4*)b)[tid];
    float4 y;
    y.x = d0 * inv * gg.x + bb.x;
    y.y = d1 * inv * gg.y + bb.y;
    y.z = d2 * inv * gg.z + bb.z;
    y.w = d3 * inv * gg.w + bb.w;
    hp[tid] = y;
}

// ---------------------------------------------------------------------------
extern "C" void kernel_launch(void* const* d_in, const int* in_sizes, int n_in,
                              void* d_out, int out_size)
{
    const float* x      = (const float*)d_in[0];
    const int*   qw     = (const int*)  d_in[1];
    const float* scales = (const float*)d_in[2];
    const float* bias   = (const float*)d_in[3];
    const float* la     = (const float*)d_in[4];   // [18][32][1024]
    const float* lb     = (const float*)d_in[5];   // [18][1024][32]
    const float* ln_g   = (const float*)d_in[6];   // [5][1024]
    const float* ln_b   = (const float*)d_in[7];
    float* out = (float*)d_out;

    float *W, *h, *t1, *t2, *up, *u;
    cudaGetSymbolAddress((void**)&W,  g_W);
    cudaGetSymbolAddress((void**)&h,  g_h);
    cudaGetSymbolAddress((void**)&t1, g_t1);
    cudaGetSymbolAddress((void**)&t2, g_t2);
    cudaGetSymbolAddress((void**)&up, g_upart);
    cudaGetSymbolAddress((void**)&u,  g_u);

    // dequant all 18 weight matrices (18*1024*1024/4 float4s)
    dequant_k<<<18432, 256>>>(qw, scales, W, 4718592);

    auto run_layer = [&](const float* in, int l, float* outp, bool relu,
                         const float* res) {
        lora_u_partial<<<dim3(64, 8), 256>>>(in, la + (size_t)l * RDIM * CDIM, up);
        lora_u_reduce<<<1024, 256>>>(up, u);
        gemm_fused<<<dim3(8, 64), 256>>>(in,
                                         W + (size_t)l * CDIM * CDIM,
                                         bias + (size_t)l * CDIM,
                                         u,
                                         lb + (size_t)l * CDIM * RDIM,
                                         res, outp, relu ? 1 : 0);
    };

    for (int blk = 0; blk < 6; ++blk) {
        const float* h_in = (blk == 0) ? x : h;
        int l = blk * 3;
        run_layer(h_in, l,     t1, true,  nullptr);
        run_layer(t1,   l + 1, t2, true,  nullptr);
        float* outp = (blk == 5) ? out : h;
        run_layer(t2,   l + 2, outp, false, h_in);   // + block residual
        if (blk < 5)
            layernorm_k<<<NROWS, 256>>>(h, ln_g + (size_t)blk * CDIM,
                                           ln_b + (size_t)blk * CDIM);
    }
}